// round 13
// baseline (speedup 1.0000x reference)
#include <cuda_runtime.h>
#include <cuda_bf16.h>
#include <cuda_fp16.h>
#include <cstdint>
#include <cstddef>

#define N_TOK   8192
#define D_IN    384
#define D_H     64
#define N_HEADS 4
#define N_CLS   6
#define N_SPLIT 4
#define LN_EPS  1e-5f
#define L2SQ    2.0813689810056077f   // (log2 e)^2

// ---------------- scratch (no allocations allowed) ----------------
__device__ float g_ss[(size_t)N_HEADS * N_TOK];                   // ||hp||^2 * L2SQ
__device__ float g_ho[(size_t)N_HEADS * N_SPLIT * N_TOK * D_H];   // partial O (unnormalized)
__device__ float g_l [(size_t)N_HEADS * N_SPLIT * N_TOK];         // partial softmax denominators
// fp16 tile images (u32 = 2 halves):
//  K image per tile: 128 rows x 36 u32 (72 fp16: d 0..63 + pad)     = 4608 u32
//  Vt image per tile: 64 d-rows x 68 u32 (136 fp16: key 0..127+pad) = 4352 u32
__device__ __align__(256) uint32_t g_k16[(size_t)N_HEADS * 64 * 4608];
__device__ __align__(256) uint32_t g_v16[(size_t)N_HEADS * 64 * 4352];

// ---------------- helpers ----------------
__device__ __forceinline__ uint32_t smem_u32(const void* p) {
    uint32_t a;
    asm("{ .reg .u64 t; cvta.to.shared.u64 t, %1; cvt.u32.u64 %0, t; }" : "=r"(a) : "l"(p));
    return a;
}
__device__ __forceinline__ float sqrtapx(float x) {
    float r; asm("sqrt.approx.f32 %0, %1;" : "=f"(r) : "f"(x)); return r;
}
__device__ __forceinline__ uint32_t f16pack(float lo, float hi) {
    uint32_t r; asm("cvt.rn.f16x2.f32 %0, %1, %2;" : "=r"(r) : "f"(hi), "f"(lo)); return r;
}
__device__ __forceinline__ uint32_t ex2x2(uint32_t h2) {
    uint32_t r; asm("ex2.approx.f16x2 %0, %1;" : "=r"(r) : "r"(h2)); return r;
}
__device__ __forceinline__ void mma16816h(float c[4], const uint32_t a[4], uint32_t b0, uint32_t b1) {
    asm volatile("mma.sync.aligned.m16n8k16.row.col.f32.f16.f16.f32 "
        "{%0,%1,%2,%3}, {%4,%5,%6,%7}, {%8,%9}, {%0,%1,%2,%3};"
        : "+f"(c[0]), "+f"(c[1]), "+f"(c[2]), "+f"(c[3])
        : "r"(a[0]), "r"(a[1]), "r"(a[2]), "r"(a[3]), "r"(b0), "r"(b1));
}
__device__ __forceinline__ void ldsm4(uint32_t r[4], uint32_t addr) {
    asm volatile("ldmatrix.sync.aligned.m8n8.x4.shared.b16 {%0,%1,%2,%3}, [%4];"
        : "=r"(r[0]), "=r"(r[1]), "=r"(r[2]), "=r"(r[3]) : "r"(addr));
}

#define MBARRIER_INIT(addr, cnt) \
    asm volatile("mbarrier.init.shared.b64 [%0], %1;" :: "r"((uint32_t)(addr)), "r"((uint32_t)(cnt)) : "memory")
#define MBARRIER_EXPECT_TX(addr, tx) \
    asm volatile("mbarrier.arrive.expect_tx.shared.b64 _, [%0], %1;" :: "r"((uint32_t)(addr)), "r"((uint32_t)(tx)) : "memory")
#define MBARRIER_ARRIVE(addr) \
    asm volatile("mbarrier.arrive.shared.b64 _, [%0];" :: "r"((uint32_t)(addr)) : "memory")
#define MBARRIER_WAIT_PARITY(addr, par) do {                                     \
    uint32_t _m = (uint32_t)(addr); uint32_t _p = (uint32_t)(par); uint32_t _d;  \
    asm volatile("{\n\t.reg .pred p;\n\t"                                        \
        "mbarrier.try_wait.parity.acquire.cta.shared::cta.b64 p, [%1], %2;\n\t"  \
        "selp.b32 %0, 1, 0, p;\n\t}" : "=r"(_d) : "r"(_m), "r"(_p) : "memory");  \
    if (!_d) {                                                                   \
        asm volatile("{\n\t.reg .pred P1;\n\t"                                   \
            "WL_%=:\n\t"                                                         \
            "mbarrier.try_wait.parity.acquire.cta.shared::cta.b64 P1, [%0], %1, 0x989680;\n\t" \
            "@P1 bra.uni WD_%=;\n\t"                                             \
            "bra.uni WL_%=;\n\t"                                                 \
            "WD_%=:\n\t}" :: "r"(_m), "r"(_p) : "memory");                       \
    }                                                                            \
} while (0)

__device__ __forceinline__ void bulk_g2s(uint32_t dst, const void* src, uint32_t bytes, uint32_t mbar) {
    asm volatile("cp.async.bulk.shared::cta.global.mbarrier::complete_tx::bytes [%0], [%1], %2, [%3];"
        :: "r"(dst), "l"(src), "r"(bytes), "r"(mbar) : "memory");
}

// ---------------------------------------------------------------------------
// Kernel 1: proj + head projections + sumsq + DIRECT fp16 image generation
// (k_prep fused: K image written from registers; Vt image via Ws-smem
//  transpose bounce after each head GEMM). g_hp eliminated.
// Block = 64 rows; tile t = blockIdx.x>>1; halfsel = blockIdx.x&1 selects
// which 64-key half of the 128-key tile this block produces.
// ---------------------------------------------------------------------------
__global__ void __launch_bounds__(256) k_proj(const float* __restrict__ x,
                                              const float* __restrict__ pw,
                                              const float* __restrict__ pb,
                                              const float* __restrict__ hw,
                                              const float* __restrict__ hb)
{
    __shared__ float As[64 * 68];
    __shared__ float Ws[64 * 64];
    const int tid = threadIdx.x;
    const int ty = tid >> 4, tx = tid & 15;
    const int row0 = blockIdx.x * 64;
    const int t = blockIdx.x >> 1;
    const int halfsel = blockIdx.x & 1;

    float acc[4][4];
#pragma unroll
    for (int i = 0; i < 4; i++)
#pragma unroll
        for (int j = 0; j < 4; j++) acc[i][j] = 0.f;

    for (int kk = 0; kk < D_IN; kk += 64) {
#pragma unroll
        for (int l = 0; l < 4; l++) {
            int idx = tid + l * 256;
            int r = idx >> 4, c = (idx & 15) << 2;
            *(float4*)&As[r * 68 + c] = *(const float4*)&x[(size_t)(row0 + r) * D_IN + kk + c];
            *(float4*)&Ws[r * 64 + c] = *(const float4*)&pw[(size_t)(kk + r) * D_H + c];
        }
        __syncthreads();
#pragma unroll 8
        for (int k = 0; k < 64; k++) {
            float a0 = As[(4 * ty + 0) * 68 + k];
            float a1 = As[(4 * ty + 1) * 68 + k];
            float a2 = As[(4 * ty + 2) * 68 + k];
            float a3 = As[(4 * ty + 3) * 68 + k];
            float4 b = *(const float4*)&Ws[k * 64 + 4 * tx];
            acc[0][0] += a0 * b.x; acc[0][1] += a0 * b.y; acc[0][2] += a0 * b.z; acc[0][3] += a0 * b.w;
            acc[1][0] += a1 * b.x; acc[1][1] += a1 * b.y; acc[1][2] += a1 * b.z; acc[1][3] += a1 * b.w;
            acc[2][0] += a2 * b.x; acc[2][1] += a2 * b.y; acc[2][2] += a2 * b.z; acc[2][3] += a2 * b.w;
            acc[3][0] += a3 * b.x; acc[3][1] += a3 * b.y; acc[3][2] += a3 * b.z; acc[3][3] += a3 * b.w;
        }
        __syncthreads();
    }
    {
        float4 pbv = *(const float4*)&pb[4 * tx];
        float pbz[4] = {pbv.x, pbv.y, pbv.z, pbv.w};
#pragma unroll
        for (int i = 0; i < 4; i++)
#pragma unroll
            for (int j = 0; j < 4; j++)
                As[(4 * ty + i) * 68 + 4 * tx + j] = fmaxf(acc[i][j] + pbz[j], 0.f);
    }
    __syncthreads();

    for (int h = 0; h < N_HEADS; h++) {
#pragma unroll
        for (int l = 0; l < 4; l++) {
            int idx = tid + l * 256;
            int r = idx >> 4, c = (idx & 15) << 2;
            *(float4*)&Ws[r * 64 + c] = *(const float4*)&hw[((size_t)h * 64 + r) * 64 + c];
        }
        __syncthreads();

        float a2c[4][4];
#pragma unroll
        for (int i = 0; i < 4; i++)
#pragma unroll
            for (int j = 0; j < 4; j++) a2c[i][j] = 0.f;

#pragma unroll 8
        for (int k = 0; k < 64; k++) {
            float a0 = As[(4 * ty + 0) * 68 + k];
            float a1 = As[(4 * ty + 1) * 68 + k];
            float a2 = As[(4 * ty + 2) * 68 + k];
            float a3 = As[(4 * ty + 3) * 68 + k];
            float4 b = *(const float4*)&Ws[k * 64 + 4 * tx];
            a2c[0][0] += a0 * b.x; a2c[0][1] += a0 * b.y; a2c[0][2] += a0 * b.z; a2c[0][3] += a0 * b.w;
            a2c[1][0] += a1 * b.x; a2c[1][1] += a1 * b.y; a2c[1][2] += a1 * b.z; a2c[1][3] += a1 * b.w;
            a2c[2][0] += a2 * b.x; a2c[2][1] += a2 * b.y; a2c[2][2] += a2 * b.z; a2c[2][3] += a2 * b.w;
            a2c[3][0] += a3 * b.x; a2c[3][1] += a3 * b.y; a2c[3][2] += a3 * b.z; a2c[3][3] += a3 * b.w;
        }

        // bias into registers
        float4 hbv = *(const float4*)&hb[h * 64 + 4 * tx];
        float hbz[4] = {hbv.x, hbv.y, hbv.z, hbv.w};
        float v[4][4];
#pragma unroll
        for (int i = 0; i < 4; i++)
#pragma unroll
            for (int j = 0; j < 4; j++) v[i][j] = a2c[i][j] + hbz[j];

        __syncthreads();   // all warps finished reading Ws (weights)

        // K image from registers + sumsq + stash hp into Ws for transpose
        uint32_t* kh = g_k16 + ((size_t)h * 64 + t) * 4608;
#pragma unroll
        for (int i = 0; i < 4; i++) {
            int row = 4 * ty + i;
            Ws[row * 64 + 4 * tx + 0] = v[i][0];
            Ws[row * 64 + 4 * tx + 1] = v[i][1];
            Ws[row * 64 + 4 * tx + 2] = v[i][2];
            Ws[row * 64 + 4 * tx + 3] = v[i][3];
            int key = halfsel * 64 + row;
            kh[key * 36 + 2 * tx]     = f16pack(v[i][0], v[i][1]);
            kh[key * 36 + 2 * tx + 1] = f16pack(v[i][2], v[i][3]);
            float rs = v[i][0] * v[i][0] + v[i][1] * v[i][1]
                     + v[i][2] * v[i][2] + v[i][3] * v[i][3];
#pragma unroll
            for (int w = 1; w < 16; w <<= 1)
                rs += __shfl_xor_sync(0xffffffffu, rs, w, 16);
            if (tx == 0) g_ss[(size_t)h * N_TOK + row0 + row] = rs * L2SQ;
        }
        __syncthreads();   // Ws now holds hp[64 rows][64 d]

        // Vt image: vh[d*68 + halfsel*32 + m] = (hp[2m][d], hp[2m+1][d])
        {
            uint32_t* vh = g_v16 + ((size_t)h * 64 + t) * 4352;
            const int d = tid & 63;
            const int mg = (tid >> 6) << 3;   // 0,8,16,24
#pragma unroll
            for (int mi = 0; mi < 8; mi++) {
                int m = mg + mi;
                vh[d * 68 + halfsel * 32 + m] =
                    f16pack(Ws[(2 * m) * 64 + d], Ws[(2 * m + 1) * 64 + d]);
            }
        }
        __syncthreads();   // done reading Ws before next head overwrites it
    }
}

// profiling alignment shim (lets ncu -s 5 land on k_attn)
__global__ void k_dummy() {}

// ---------------------------------------------------------------------------
// Kernel 2: split-K distance flash-attention, 16 consumer warps (4/SMSP).
//  (round-11 winner config, N_STAGES=4)
// ---------------------------------------------------------------------------
#define SM_FULL(s)  ((s) * 8)
#define SM_EMPTY(s) (32 + (s) * 8)
#define SM_Q       128
#define SM_STG     (SM_Q + 18432)            // 18560
#define OFF_K16    0
#define OFF_V16    18432
#define OFF_KK     35840
#define STG_BYTES  36352
#define N_STAGES   4
#define T_PER_CTA  16
#define SM_TOTAL   (SM_STG + N_STAGES * STG_BYTES)   // 163968

__global__ void __launch_bounds__(544, 1) k_attn()
{
    extern __shared__ char smem[];
    const uint32_t sb = smem_u32(smem);
    const int tid  = threadIdx.x;
    const int warp = tid >> 5;
    const int lane = tid & 31;
    const int head = blockIdx.y;
    const int split = blockIdx.z;
    const int q0 = blockIdx.x * 128;
    const int t0 = split * T_PER_CTA;
    const float* ssq = g_ss + (size_t)head * N_TOK;

    if (tid == 0) {
#pragma unroll
        for (int s = 0; s < N_STAGES; s++) {
            MBARRIER_INIT(sb + SM_FULL(s), 1);
            MBARRIER_INIT(sb + SM_EMPTY(s), 16);
        }
    }

    // Q image resident in smem for the whole CTA
    {
        const uint4* sh = (const uint4*)(g_k16 + ((size_t)head * 64 + blockIdx.x) * 4608);
        uint4* dh = (uint4*)(smem + SM_Q);
        for (int i = tid; i < 1152; i += 544) dh[i] = sh[i];
    }
    __syncthreads();

    const int w7 = warp & 7;
    const int khalf = (warp & 8) ? 64 : 0;
    const int g  = lane >> 2;
    const int lt = lane & 3;
    const int mm = lane >> 3;
    const int r8 = lane & 7;
    const int q_dsel = (mm >> 1) * 16;
    const int k_dsel = (mm & 1) * 16;
    const int k_rowofs = r8 + (mm >> 1) * 8;
    const int q_row = 16 * w7 + r8 + (mm & 1) * 8;

    const int r0g = q0 + 16 * w7 + g;
    const int r1g = r0g + 8;

    const uint32_t ones_frag = ((lane >> 2) == 0) ? 0x3C003C00u : 0u;

    float O[8][4];
#pragma unroll
    for (int n = 0; n < 8; n++)
#pragma unroll
        for (int e = 0; e < 4; e++) O[n][e] = 0.f;
    float Ol[4] = {0.f, 0.f, 0.f, 0.f};

    if (warp == 16) {
        // ---------------- producer warp ----------------
        if (lane == 0) {
            const size_t hb = (size_t)head * 64 + t0;
#pragma unroll
            for (int i = 0; i < N_STAGES; i++) {
                const uint32_t st = sb + SM_STG + i * STG_BYTES;
                MBARRIER_EXPECT_TX(sb + SM_FULL(i), STG_BYTES);
                bulk_g2s(st + OFF_K16, g_k16 + (hb + i) * 4608, 18432, sb + SM_FULL(i));
                bulk_g2s(st + OFF_V16, g_v16 + (hb + i) * 4352, 17408, sb + SM_FULL(i));
                bulk_g2s(st + OFF_KK,  ssq + (size_t)(t0 + i) * 128, 512, sb + SM_FULL(i));
            }
            int s = 0, pe = 0;
            for (int i = N_STAGES; i < T_PER_CTA; i++) {
                MBARRIER_WAIT_PARITY(sb + SM_EMPTY(s), pe);
                const uint32_t st = sb + SM_STG + s * STG_BYTES;
                MBARRIER_EXPECT_TX(sb + SM_FULL(s), STG_BYTES);
                bulk_g2s(st + OFF_K16, g_k16 + (hb + i) * 4608, 18432, sb + SM_FULL(s));
                bulk_g2s(st + OFF_V16, g_v16 + (hb + i) * 4352, 17408, sb + SM_FULL(s));
                bulk_g2s(st + OFF_KK,  ssq + (size_t)(t0 + i) * 128, 512, sb + SM_FULL(s));
                if (++s == N_STAGES) { s = 0; pe ^= 1; }
            }
        }
    } else {
        // ---------------- consumer warps (0..15) ----------------
        const float qq0 = ssq[r0g];     // already *L2SQ
        const float qq1 = ssq[r1g];
        const float N2L = -2.f * L2SQ;

        int s = 0, ph = 0;
        for (int i = 0; i < T_PER_CTA; i++) {
            const int t = t0 + i;
            MBARRIER_WAIT_PARITY(sb + SM_FULL(s), ph);
            const uint32_t stg = sb + SM_STG + s * STG_BYTES;

            // ---- GEMM1: S = Q.K, fp16 single product ----
            float S[8][4];
#pragma unroll
            for (int n = 0; n < 8; n++)
#pragma unroll
                for (int e = 0; e < 4; e++) S[n][e] = 0.f;

#pragma unroll
            for (int kc = 0; kc < 4; kc++) {
                uint32_t qh[4];
                ldsm4(qh, sb + SM_Q + q_row * 144 + kc * 32 + q_dsel);
#pragma unroll
                for (int np = 0; np < 4; np++) {
                    uint32_t kb[4];
                    ldsm4(kb, stg + OFF_K16 + (khalf + 16 * np + k_rowofs) * 144 + kc * 32 + k_dsel);
                    mma16816h(S[2 * np],     qh, kb[0], kb[1]);
                    mma16816h(S[2 * np + 1], qh, kb[2], kb[3]);
                }
            }

            // ---- GEMM2 with interleaved f16x2 softmax epilogue ----
            const float* kkp = (const float*)(smem + SM_STG + s * STG_BYTES + OFF_KK);
            const bool dt = (t == (int)blockIdx.x);   // only tile that can hold the diagonal
            const int kt = t * 128;
#pragma unroll
            for (int kc2 = 0; kc2 < 4; kc2++) {
                uint32_t aF[4];
#pragma unroll
                for (int u = 0; u < 2; u++) {
                    const int nt = 2 * kc2 + u;
                    float2 kkv = *(const float2*)(kkp + khalf + 8 * nt + 2 * lt);
                    float d00 = 0.f - sqrtapx(fmaxf(fmaf(S[nt][0], N2L, qq0 + kkv.x), 0.f));
                    float d01 = 0.f - sqrtapx(fmaxf(fmaf(S[nt][1], N2L, qq0 + kkv.y), 0.f));
                    float d10 = 0.f - sqrtapx(fmaxf(fmaf(S[nt][2], N2L, qq1 + kkv.x), 0.f));
                    float d11 = 0.f - sqrtapx(fmaxf(fmaf(S[nt][3], N2L, qq1 + kkv.y), 0.f));
                    if (dt) {
                        const int colg = kt + khalf + 8 * nt + 2 * lt;
                        if (colg == r0g)     d00 = 0.f;
                        if (colg + 1 == r0g) d01 = 0.f;
                        if (colg == r1g)     d10 = 0.f;
                        if (colg + 1 == r1g) d11 = 0.f;
                    }
                    aF[2 * u]     = ex2x2(f16pack(d00, d01));
                    aF[2 * u + 1] = ex2x2(f16pack(d10, d11));
                }
                mma16816h(Ol, aF, ones_frag, ones_frag);
#pragma unroll
                for (int j = 0; j < 4; j++) {
                    uint32_t vb[4];
                    uint32_t va = stg + OFF_V16 + (16 * j + k_rowofs) * 272
                                + (khalf + 16 * kc2) * 2 + k_dsel;
                    ldsm4(vb, va);
                    mma16816h(O[2 * j],     aF, vb[0], vb[1]);
                    mma16816h(O[2 * j + 1], aF, vb[2], vb[3]);
                }
            }

            if (lane == 0) MBARRIER_ARRIVE(sb + SM_EMPTY(s));
            if (++s == N_STAGES) { s = 0; ph ^= 1; }
        }
    }

    // ---- cross-half reduction through (now free) stage smem ----
    __syncthreads();
    float* red  = (float*)(smem + SM_STG);             // 8 * 16 * 64 floats = 32KB
    float* lred = (float*)(smem + SM_STG + 32768);     // 8 * 16 floats

    if (warp >= 8 && warp < 16) {
#pragma unroll
        for (int n = 0; n < 8; n++)
#pragma unroll
            for (int e = 0; e < 4; e++) {
                int row = g + ((e >> 1) << 3);
                int col = 8 * n + 2 * lt + (e & 1);
                red[w7 * 1024 + row * 64 + col] = O[n][e];
            }
        if (lt == 0) {
            lred[w7 * 16 + g] = Ol[0];
            lred[w7 * 16 + g + 8] = Ol[2];
        }
    }
    __syncthreads();

    if (warp < 8) {
#pragma unroll
        for (int n = 0; n < 8; n++)
#pragma unroll
            for (int e = 0; e < 4; e++) {
                int row = g + ((e >> 1) << 3);
                int col = 8 * n + 2 * lt + (e & 1);
                O[n][e] += red[w7 * 1024 + row * 64 + col];
            }

        const size_t pbase = ((size_t)head * N_SPLIT + split) * N_TOK;
        if (lt == 0) {
            g_l[pbase + r0g] = Ol[0] + lred[w7 * 16 + g];
            g_l[pbase + r1g] = Ol[2] + lred[w7 * 16 + g + 8];
        }
        float* dst0 = g_ho + (pbase + r0g) * D_H;
        float* dst1 = g_ho + (pbase + r1g) * D_H;
#pragma unroll
        for (int n = 0; n < 8; n++) {
            *(float2*)&dst0[8 * n + 2 * lt] = make_float2(O[n][0], O[n][1]);
            *(float2*)&dst1[8 * n + 2 * lt] = make_float2(O[n][2], O[n][3]);
        }
    }
}

// ---------------------------------------------------------------------------
// Kernel 3: combine split partials + heads, LayerNorm, FC (unchanged)
// ---------------------------------------------------------------------------
__global__ void __launch_bounds__(256) k_final(const float* __restrict__ attn_w,
                                               const float* __restrict__ gamma,
                                               const float* __restrict__ beta,
                                               const float* __restrict__ fcw,
                                               const float* __restrict__ fcb,
                                               float* __restrict__ out)
{
    const int warp = threadIdx.x >> 5;
    const int lane = threadIdx.x & 31;
    const int row = blockIdx.x * 8 + warp;

    float a0 = attn_w[0], a1 = attn_w[1], a2 = attn_w[2], a3 = attn_w[3];
    float mx = fmaxf(fmaxf(a0, a1), fmaxf(a2, a3));
    float aw[4];
    aw[0] = __expf(a0 - mx); aw[1] = __expf(a1 - mx);
    aw[2] = __expf(a2 - mx); aw[3] = __expf(a3 - mx);
    float ainv = 1.f / (aw[0] + aw[1] + aw[2] + aw[3]);

    const int d0 = lane, d1 = lane + 32;
    float c0 = 0.f, c1 = 0.f;
#pragma unroll
    for (int h = 0; h < N_HEADS; h++) {
        float lsum = 0.f;
        float o0 = 0.f, o1 = 0.f;
#pragma unroll
        for (int s = 0; s < N_SPLIT; s++) {
            const size_t pbase = ((size_t)h * N_SPLIT + s) * N_TOK + row;
            lsum += g_l[pbase];
            const float* p = g_ho + pbase * D_H;
            o0 += p[d0];
            o1 += p[d1];
        }
        float w = aw[h] / lsum;
        c0 += w * o0;
        c1 += w * o1;
    }
    c0 *= ainv; c1 *= ainv;

    float s = c0 + c1;
#pragma unroll
    for (int w = 16; w; w >>= 1) s += __shfl_xor_sync(0xffffffffu, s, w);
    float mu = s * (1.f / 64.f);
    float v0 = c0 - mu, v1 = c1 - mu;
    float vv = v0 * v0 + v1 * v1;
#pragma unroll
    for (int w = 16; w; w >>= 1) vv += __shfl_xor_sync(0xffffffffu, vv, w);
    float inv = rsqrtf(vv * (1.f / 64.f) + LN_EPS);
    float n0 = v0 * inv * gamma[d0] + beta[d0];
    float n1 = v1 * inv * gamma[d1] + beta[d1];

    float o[N_CLS];
#pragma unroll
    for (int c = 0; c < N_CLS; c++)
        o[c] = n0 * fcw[d0 * N_CLS + c] + n1 * fcw[d1 * N_CLS + c];
#pragma unroll
    for (int c = 0; c < N_CLS; c++)
#pragma unroll
        for (int w = 16; w; w >>= 1) o[c] += __shfl_xor_sync(0xffffffffu, o[c], w);

    if (lane == 0) {
#pragma unroll
        for (int c = 0; c < N_CLS; c++)
            out[(size_t)row * N_CLS + c] = o[c] + fcb[c];
    }
}

// ---------------------------------------------------------------------------
extern "C" void kernel_launch(void* const* d_in, const int* in_sizes, int n_in,
                              void* d_out, int out_size)
{
    const float* x      = (const float*)d_in[0];
    const float* proj_w = (const float*)d_in[1];
    const float* proj_b = (const float*)d_in[2];
    const float* head_w = (const float*)d_in[3];
    const float* head_b = (const float*)d_in[4];
    const float* attn_w = (const float*)d_in[5];
    const float* gamma  = (const float*)d_in[6];
    const float* beta   = (const float*)d_in[7];
    const float* fc_w   = (const float*)d_in[8];
    const float* fc_b   = (const float*)d_in[9];
    float* out = (float*)d_out;

    static int smem_set = 0;
    if (!smem_set) {
        cudaFuncSetAttribute(k_attn, cudaFuncAttributeMaxDynamicSharedMemorySize, SM_TOTAL);
        smem_set = 1;
    }

    k_proj<<<N_TOK / 64, 256>>>(x, proj_w, proj_b, head_w, head_b);

    k_dummy<<<1, 32>>>();
    k_dummy<<<1, 32>>>();   // aligns ncu -s 5 onto k_attn (k_prep launch removed)

    dim3 g2(N_TOK / 128, N_HEADS, N_SPLIT);
    k_attn<<<g2, 544, SM_TOTAL>>>();

    k_final<<<N_TOK / 8, 256>>>(attn_w, gamma, beta, fc_w, fc_b, out);
}

// round 14
// speedup vs baseline: 1.5748x; 1.5748x over previous
#include <cuda_runtime.h>
#include <cuda_bf16.h>
#include <cuda_fp16.h>
#include <cstdint>
#include <cstddef>

#define N_TOK   8192
#define D_IN    384
#define D_H     64
#define N_HEADS 4
#define N_CLS   6
#define N_SPLIT 4
#define LN_EPS  1e-5f
#define L2SQ    2.0813689810056077f   // (log2 e)^2

// ---------------- scratch (no allocations allowed) ----------------
__device__ float g_ss[(size_t)N_HEADS * N_TOK];                   // ||hp||^2 * L2SQ
__device__ float g_ho[(size_t)N_HEADS * N_SPLIT * N_TOK * D_H];   // partial O (unnormalized)
__device__ float g_l [(size_t)N_HEADS * N_SPLIT * N_TOK];         // partial softmax denominators
// fp16 tile images (u32 = 2 halves):
//  K image per tile: 128 rows x 36 u32 (72 fp16: d 0..63 + pad)     = 4608 u32
//  Vt image per tile: 64 d-rows x 68 u32 (136 fp16: key 0..127+pad) = 4352 u32
__device__ __align__(256) uint32_t g_k16[(size_t)N_HEADS * 64 * 4608];
__device__ __align__(256) uint32_t g_v16[(size_t)N_HEADS * 64 * 4352];

// ---------------- helpers ----------------
__device__ __forceinline__ uint32_t smem_u32(const void* p) {
    uint32_t a;
    asm("{ .reg .u64 t; cvta.to.shared.u64 t, %1; cvt.u32.u64 %0, t; }" : "=r"(a) : "l"(p));
    return a;
}
__device__ __forceinline__ float sqrtapx(float x) {
    float r; asm("sqrt.approx.f32 %0, %1;" : "=f"(r) : "f"(x)); return r;
}
__device__ __forceinline__ uint32_t f16pack(float lo, float hi) {
    uint32_t r; asm("cvt.rn.f16x2.f32 %0, %1, %2;" : "=r"(r) : "f"(hi), "f"(lo)); return r;
}
__device__ __forceinline__ uint32_t ex2x2(uint32_t h2) {
    uint32_t r; asm("ex2.approx.f16x2 %0, %1;" : "=r"(r) : "r"(h2)); return r;
}
__device__ __forceinline__ void mma16816h(float c[4], const uint32_t a[4], uint32_t b0, uint32_t b1) {
    asm volatile("mma.sync.aligned.m16n8k16.row.col.f32.f16.f16.f32 "
        "{%0,%1,%2,%3}, {%4,%5,%6,%7}, {%8,%9}, {%0,%1,%2,%3};"
        : "+f"(c[0]), "+f"(c[1]), "+f"(c[2]), "+f"(c[3])
        : "r"(a[0]), "r"(a[1]), "r"(a[2]), "r"(a[3]), "r"(b0), "r"(b1));
}
__device__ __forceinline__ void ldsm4(uint32_t r[4], uint32_t addr) {
    asm volatile("ldmatrix.sync.aligned.m8n8.x4.shared.b16 {%0,%1,%2,%3}, [%4];"
        : "=r"(r[0]), "=r"(r[1]), "=r"(r[2]), "=r"(r[3]) : "r"(addr));
}

#define MBARRIER_INIT(addr, cnt) \
    asm volatile("mbarrier.init.shared.b64 [%0], %1;" :: "r"((uint32_t)(addr)), "r"((uint32_t)(cnt)) : "memory")
#define MBARRIER_EXPECT_TX(addr, tx) \
    asm volatile("mbarrier.arrive.expect_tx.shared.b64 _, [%0], %1;" :: "r"((uint32_t)(addr)), "r"((uint32_t)(tx)) : "memory")
#define MBARRIER_ARRIVE(addr) \
    asm volatile("mbarrier.arrive.shared.b64 _, [%0];" :: "r"((uint32_t)(addr)) : "memory")
#define MBARRIER_WAIT_PARITY(addr, par) do {                                     \
    uint32_t _m = (uint32_t)(addr); uint32_t _p = (uint32_t)(par); uint32_t _d;  \
    asm volatile("{\n\t.reg .pred p;\n\t"                                        \
        "mbarrier.try_wait.parity.acquire.cta.shared::cta.b64 p, [%1], %2;\n\t"  \
        "selp.b32 %0, 1, 0, p;\n\t}" : "=r"(_d) : "r"(_m), "r"(_p) : "memory");  \
    if (!_d) {                                                                   \
        asm volatile("{\n\t.reg .pred P1;\n\t"                                   \
            "WL_%=:\n\t"                                                         \
            "mbarrier.try_wait.parity.acquire.cta.shared::cta.b64 P1, [%0], %1, 0x989680;\n\t" \
            "@P1 bra.uni WD_%=;\n\t"                                             \
            "bra.uni WL_%=;\n\t"                                                 \
            "WD_%=:\n\t}" :: "r"(_m), "r"(_p) : "memory");                       \
    }                                                                            \
} while (0)

__device__ __forceinline__ void bulk_g2s(uint32_t dst, const void* src, uint32_t bytes, uint32_t mbar) {
    asm volatile("cp.async.bulk.shared::cta.global.mbarrier::complete_tx::bytes [%0], [%1], %2, [%3];"
        :: "r"(dst), "l"(src), "r"(bytes), "r"(mbar) : "memory");
}

// ---------------------------------------------------------------------------
// Kernel 1: proj + head projections + sumsq + fused fp16 image generation
// (K image from registers; Vt image via Ws-smem transpose bounce).
// Block = 64 rows; t = blockIdx.x>>1; halfsel = blockIdx.x&1.
// ---------------------------------------------------------------------------
__global__ void __launch_bounds__(256) k_proj(const float* __restrict__ x,
                                              const float* __restrict__ pw,
                                              const float* __restrict__ pb,
                                              const float* __restrict__ hw,
                                              const float* __restrict__ hb)
{
    __shared__ float As[64 * 68];
    __shared__ float Ws[64 * 64];
    const int tid = threadIdx.x;
    const int ty = tid >> 4, tx = tid & 15;
    const int row0 = blockIdx.x * 64;
    const int t = blockIdx.x >> 1;
    const int halfsel = blockIdx.x & 1;

    float acc[4][4];
#pragma unroll
    for (int i = 0; i < 4; i++)
#pragma unroll
        for (int j = 0; j < 4; j++) acc[i][j] = 0.f;

    for (int kk = 0; kk < D_IN; kk += 64) {
#pragma unroll
        for (int l = 0; l < 4; l++) {
            int idx = tid + l * 256;
            int r = idx >> 4, c = (idx & 15) << 2;
            *(float4*)&As[r * 68 + c] = *(const float4*)&x[(size_t)(row0 + r) * D_IN + kk + c];
            *(float4*)&Ws[r * 64 + c] = *(const float4*)&pw[(size_t)(kk + r) * D_H + c];
        }
        __syncthreads();
#pragma unroll 8
        for (int k = 0; k < 64; k++) {
            float a0 = As[(4 * ty + 0) * 68 + k];
            float a1 = As[(4 * ty + 1) * 68 + k];
            float a2 = As[(4 * ty + 2) * 68 + k];
            float a3 = As[(4 * ty + 3) * 68 + k];
            float4 b = *(const float4*)&Ws[k * 64 + 4 * tx];
            acc[0][0] += a0 * b.x; acc[0][1] += a0 * b.y; acc[0][2] += a0 * b.z; acc[0][3] += a0 * b.w;
            acc[1][0] += a1 * b.x; acc[1][1] += a1 * b.y; acc[1][2] += a1 * b.z; acc[1][3] += a1 * b.w;
            acc[2][0] += a2 * b.x; acc[2][1] += a2 * b.y; acc[2][2] += a2 * b.z; acc[2][3] += a2 * b.w;
            acc[3][0] += a3 * b.x; acc[3][1] += a3 * b.y; acc[3][2] += a3 * b.z; acc[3][3] += a3 * b.w;
        }
        __syncthreads();
    }
    {
        float4 pbv = *(const float4*)&pb[4 * tx];
        float pbz[4] = {pbv.x, pbv.y, pbv.z, pbv.w};
#pragma unroll
        for (int i = 0; i < 4; i++)
#pragma unroll
            for (int j = 0; j < 4; j++)
                As[(4 * ty + i) * 68 + 4 * tx + j] = fmaxf(acc[i][j] + pbz[j], 0.f);
    }
    __syncthreads();

    for (int h = 0; h < N_HEADS; h++) {
#pragma unroll
        for (int l = 0; l < 4; l++) {
            int idx = tid + l * 256;
            int r = idx >> 4, c = (idx & 15) << 2;
            *(float4*)&Ws[r * 64 + c] = *(const float4*)&hw[((size_t)h * 64 + r) * 64 + c];
        }
        __syncthreads();

        float a2c[4][4];
#pragma unroll
        for (int i = 0; i < 4; i++)
#pragma unroll
            for (int j = 0; j < 4; j++) a2c[i][j] = 0.f;

#pragma unroll 8
        for (int k = 0; k < 64; k++) {
            float a0 = As[(4 * ty + 0) * 68 + k];
            float a1 = As[(4 * ty + 1) * 68 + k];
            float a2 = As[(4 * ty + 2) * 68 + k];
            float a3 = As[(4 * ty + 3) * 68 + k];
            float4 b = *(const float4*)&Ws[k * 64 + 4 * tx];
            a2c[0][0] += a0 * b.x; a2c[0][1] += a0 * b.y; a2c[0][2] += a0 * b.z; a2c[0][3] += a0 * b.w;
            a2c[1][0] += a1 * b.x; a2c[1][1] += a1 * b.y; a2c[1][2] += a1 * b.z; a2c[1][3] += a1 * b.w;
            a2c[2][0] += a2 * b.x; a2c[2][1] += a2 * b.y; a2c[2][2] += a2 * b.z; a2c[2][3] += a2 * b.w;
            a2c[3][0] += a3 * b.x; a2c[3][1] += a3 * b.y; a2c[3][2] += a3 * b.z; a2c[3][3] += a3 * b.w;
        }

        float4 hbv = *(const float4*)&hb[h * 64 + 4 * tx];
        float hbz[4] = {hbv.x, hbv.y, hbv.z, hbv.w};
        float v[4][4];
#pragma unroll
        for (int i = 0; i < 4; i++)
#pragma unroll
            for (int j = 0; j < 4; j++) v[i][j] = a2c[i][j] + hbz[j];

        __syncthreads();   // all warps finished reading Ws (weights)

        // K image from registers + sumsq + stash hp into Ws for transpose
        uint32_t* kh = g_k16 + ((size_t)h * 64 + t) * 4608;
#pragma unroll
        for (int i = 0; i < 4; i++) {
            int row = 4 * ty + i;
            Ws[row * 64 + 4 * tx + 0] = v[i][0];
            Ws[row * 64 + 4 * tx + 1] = v[i][1];
            Ws[row * 64 + 4 * tx + 2] = v[i][2];
            Ws[row * 64 + 4 * tx + 3] = v[i][3];
            int key = halfsel * 64 + row;
            kh[key * 36 + 2 * tx]     = f16pack(v[i][0], v[i][1]);
            kh[key * 36 + 2 * tx + 1] = f16pack(v[i][2], v[i][3]);
            float rs = v[i][0] * v[i][0] + v[i][1] * v[i][1]
                     + v[i][2] * v[i][2] + v[i][3] * v[i][3];
#pragma unroll
            for (int w = 1; w < 16; w <<= 1)
                rs += __shfl_xor_sync(0xffffffffu, rs, w, 16);
            if (tx == 0) g_ss[(size_t)h * N_TOK + row0 + row] = rs * L2SQ;
        }
        __syncthreads();   // Ws now holds hp[64 rows][64 d]

        // Vt image: vh[d*68 + halfsel*32 + m] = (hp[2m][d], hp[2m+1][d])
        {
            uint32_t* vh = g_v16 + ((size_t)h * 64 + t) * 4352;
            const int d = tid & 63;
            const int mg = (tid >> 6) << 3;   // 0,8,16,24
#pragma unroll
            for (int mi = 0; mi < 8; mi++) {
                int m = mg + mi;
                vh[d * 68 + halfsel * 32 + m] =
                    f16pack(Ws[(2 * m) * 64 + d], Ws[(2 * m + 1) * 64 + d]);
            }
        }
        __syncthreads();   // done reading Ws before next head overwrites it
    }
}

// profiling alignment shim (lets ncu -s 5 land on k_attn)
__global__ void k_dummy() {}

// ---------------------------------------------------------------------------
// Kernel 2: split-K distance flash-attention, 16 consumer warps (4/SMSP).
//  EXACT round-11 winner config: N_STAGES=3, smem 127616 (do NOT grow smem —
//  164KB/4-stage variant regressed k_attn 235us -> 374us).
// ---------------------------------------------------------------------------
#define SM_FULL(s)  ((s) * 8)
#define SM_EMPTY(s) (24 + (s) * 8)
#define SM_Q       128
#define SM_STG     (SM_Q + 18432)            // 18560
#define OFF_K16    0
#define OFF_V16    18432
#define OFF_KK     35840
#define STG_BYTES  36352
#define N_STAGES   3
#define T_PER_CTA  16
#define SM_TOTAL   (SM_STG + N_STAGES * STG_BYTES)   // 127616

__global__ void __launch_bounds__(544, 1) k_attn()
{
    extern __shared__ char smem[];
    const uint32_t sb = smem_u32(smem);
    const int tid  = threadIdx.x;
    const int warp = tid >> 5;
    const int lane = tid & 31;
    const int head = blockIdx.y;
    const int split = blockIdx.z;
    const int q0 = blockIdx.x * 128;
    const int t0 = split * T_PER_CTA;
    const float* ssq = g_ss + (size_t)head * N_TOK;

    if (tid == 0) {
#pragma unroll
        for (int s = 0; s < N_STAGES; s++) {
            MBARRIER_INIT(sb + SM_FULL(s), 1);
            MBARRIER_INIT(sb + SM_EMPTY(s), 16);
        }
    }

    // Q image resident in smem for the whole CTA
    {
        const uint4* sh = (const uint4*)(g_k16 + ((size_t)head * 64 + blockIdx.x) * 4608);
        uint4* dh = (uint4*)(smem + SM_Q);
        for (int i = tid; i < 1152; i += 544) dh[i] = sh[i];
    }
    __syncthreads();

    const int w7 = warp & 7;
    const int khalf = (warp & 8) ? 64 : 0;
    const int g  = lane >> 2;
    const int lt = lane & 3;
    const int mm = lane >> 3;
    const int r8 = lane & 7;
    const int q_dsel = (mm >> 1) * 16;
    const int k_dsel = (mm & 1) * 16;
    const int k_rowofs = r8 + (mm >> 1) * 8;
    const int q_row = 16 * w7 + r8 + (mm & 1) * 8;

    const int r0g = q0 + 16 * w7 + g;
    const int r1g = r0g + 8;

    const uint32_t ones_frag = ((lane >> 2) == 0) ? 0x3C003C00u : 0u;

    float O[8][4];
#pragma unroll
    for (int n = 0; n < 8; n++)
#pragma unroll
        for (int e = 0; e < 4; e++) O[n][e] = 0.f;
    float Ol[4] = {0.f, 0.f, 0.f, 0.f};

    if (warp == 16) {
        // ---------------- producer warp ----------------
        if (lane == 0) {
            const size_t hb = (size_t)head * 64 + t0;
#pragma unroll
            for (int i = 0; i < N_STAGES; i++) {
                const uint32_t st = sb + SM_STG + i * STG_BYTES;
                MBARRIER_EXPECT_TX(sb + SM_FULL(i), STG_BYTES);
                bulk_g2s(st + OFF_K16, g_k16 + (hb + i) * 4608, 18432, sb + SM_FULL(i));
                bulk_g2s(st + OFF_V16, g_v16 + (hb + i) * 4352, 17408, sb + SM_FULL(i));
                bulk_g2s(st + OFF_KK,  ssq + (size_t)(t0 + i) * 128, 512, sb + SM_FULL(i));
            }
            int s = 0, pe = 0;
            for (int i = N_STAGES; i < T_PER_CTA; i++) {
                MBARRIER_WAIT_PARITY(sb + SM_EMPTY(s), pe);
                const uint32_t st = sb + SM_STG + s * STG_BYTES;
                MBARRIER_EXPECT_TX(sb + SM_FULL(s), STG_BYTES);
                bulk_g2s(st + OFF_K16, g_k16 + (hb + i) * 4608, 18432, sb + SM_FULL(s));
                bulk_g2s(st + OFF_V16, g_v16 + (hb + i) * 4352, 17408, sb + SM_FULL(s));
                bulk_g2s(st + OFF_KK,  ssq + (size_t)(t0 + i) * 128, 512, sb + SM_FULL(s));
                if (++s == N_STAGES) { s = 0; pe ^= 1; }
            }
        }
    } else {
        // ---------------- consumer warps (0..15) ----------------
        const float qq0 = ssq[r0g];     // already *L2SQ
        const float qq1 = ssq[r1g];
        const float N2L = -2.f * L2SQ;

        int s = 0, ph = 0;
        for (int i = 0; i < T_PER_CTA; i++) {
            const int t = t0 + i;
            MBARRIER_WAIT_PARITY(sb + SM_FULL(s), ph);
            const uint32_t stg = sb + SM_STG + s * STG_BYTES;

            // ---- GEMM1: S = Q.K, fp16 single product ----
            float S[8][4];
#pragma unroll
            for (int n = 0; n < 8; n++)
#pragma unroll
                for (int e = 0; e < 4; e++) S[n][e] = 0.f;

#pragma unroll
            for (int kc = 0; kc < 4; kc++) {
                uint32_t qh[4];
                ldsm4(qh, sb + SM_Q + q_row * 144 + kc * 32 + q_dsel);
#pragma unroll
                for (int np = 0; np < 4; np++) {
                    uint32_t kb[4];
                    ldsm4(kb, stg + OFF_K16 + (khalf + 16 * np + k_rowofs) * 144 + kc * 32 + k_dsel);
                    mma16816h(S[2 * np],     qh, kb[0], kb[1]);
                    mma16816h(S[2 * np + 1], qh, kb[2], kb[3]);
                }
            }

            // ---- GEMM2 with interleaved f16x2 softmax epilogue ----
            const float* kkp = (const float*)(smem + SM_STG + s * STG_BYTES + OFF_KK);
            const bool dt = (t == (int)blockIdx.x);   // only tile that can hold the diagonal
            const int kt = t * 128;
#pragma unroll
            for (int kc2 = 0; kc2 < 4; kc2++) {
                uint32_t aF[4];
#pragma unroll
                for (int u = 0; u < 2; u++) {
                    const int nt = 2 * kc2 + u;
                    float2 kkv = *(const float2*)(kkp + khalf + 8 * nt + 2 * lt);
                    float d00 = 0.f - sqrtapx(fmaxf(fmaf(S[nt][0], N2L, qq0 + kkv.x), 0.f));
                    float d01 = 0.f - sqrtapx(fmaxf(fmaf(S[nt][1], N2L, qq0 + kkv.y), 0.f));
                    float d10 = 0.f - sqrtapx(fmaxf(fmaf(S[nt][2], N2L, qq1 + kkv.x), 0.f));
                    float d11 = 0.f - sqrtapx(fmaxf(fmaf(S[nt][3], N2L, qq1 + kkv.y), 0.f));
                    if (dt) {
                        const int colg = kt + khalf + 8 * nt + 2 * lt;
                        if (colg == r0g)     d00 = 0.f;
                        if (colg + 1 == r0g) d01 = 0.f;
                        if (colg == r1g)     d10 = 0.f;
                        if (colg + 1 == r1g) d11 = 0.f;
                    }
                    aF[2 * u]     = ex2x2(f16pack(d00, d01));
                    aF[2 * u + 1] = ex2x2(f16pack(d10, d11));
                }
                mma16816h(Ol, aF, ones_frag, ones_frag);
#pragma unroll
                for (int j = 0; j < 4; j++) {
                    uint32_t vb[4];
                    uint32_t va = stg + OFF_V16 + (16 * j + k_rowofs) * 272
                                + (khalf + 16 * kc2) * 2 + k_dsel;
                    ldsm4(vb, va);
                    mma16816h(O[2 * j],     aF, vb[0], vb[1]);
                    mma16816h(O[2 * j + 1], aF, vb[2], vb[3]);
                }
            }

            if (lane == 0) MBARRIER_ARRIVE(sb + SM_EMPTY(s));
            if (++s == N_STAGES) { s = 0; ph ^= 1; }
        }
    }

    // ---- cross-half reduction through (now free) stage smem ----
    __syncthreads();
    float* red  = (float*)(smem + SM_STG);             // 8 * 16 * 64 floats = 32KB
    float* lred = (float*)(smem + SM_STG + 32768);     // 8 * 16 floats

    if (warp >= 8 && warp < 16) {
#pragma unroll
        for (int n = 0; n < 8; n++)
#pragma unroll
            for (int e = 0; e < 4; e++) {
                int row = g + ((e >> 1) << 3);
                int col = 8 * n + 2 * lt + (e & 1);
                red[w7 * 1024 + row * 64 + col] = O[n][e];
            }
        if (lt == 0) {
            lred[w7 * 16 + g] = Ol[0];
            lred[w7 * 16 + g + 8] = Ol[2];
        }
    }
    __syncthreads();

    if (warp < 8) {
#pragma unroll
        for (int n = 0; n < 8; n++)
#pragma unroll
            for (int e = 0; e < 4; e++) {
                int row = g + ((e >> 1) << 3);
                int col = 8 * n + 2 * lt + (e & 1);
                O[n][e] += red[w7 * 1024 + row * 64 + col];
            }

        const size_t pbase = ((size_t)head * N_SPLIT + split) * N_TOK;
        if (lt == 0) {
            g_l[pbase + r0g] = Ol[0] + lred[w7 * 16 + g];
            g_l[pbase + r1g] = Ol[2] + lred[w7 * 16 + g + 8];
        }
        float* dst0 = g_ho + (pbase + r0g) * D_H;
        float* dst1 = g_ho + (pbase + r1g) * D_H;
#pragma unroll
        for (int n = 0; n < 8; n++) {
            *(float2*)&dst0[8 * n + 2 * lt] = make_float2(O[n][0], O[n][1]);
            *(float2*)&dst1[8 * n + 2 * lt] = make_float2(O[n][2], O[n][3]);
        }
    }
}

// ---------------------------------------------------------------------------
// Kernel 3: combine split partials + heads, LayerNorm, FC (unchanged)
// ---------------------------------------------------------------------------
__global__ void __launch_bounds__(256) k_final(const float* __restrict__ attn_w,
                                               const float* __restrict__ gamma,
                                               const float* __restrict__ beta,
                                               const float* __restrict__ fcw,
                                               const float* __restrict__ fcb,
                                               float* __restrict__ out)
{
    const int warp = threadIdx.x >> 5;
    const int lane = threadIdx.x & 31;
    const int row = blockIdx.x * 8 + warp;

    float a0 = attn_w[0], a1 = attn_w[1], a2 = attn_w[2], a3 = attn_w[3];
    float mx = fmaxf(fmaxf(a0, a1), fmaxf(a2, a3));
    float aw[4];
    aw[0] = __expf(a0 - mx); aw[1] = __expf(a1 - mx);
    aw[2] = __expf(a2 - mx); aw[3] = __expf(a3 - mx);
    float ainv = 1.f / (aw[0] + aw[1] + aw[2] + aw[3]);

    const int d0 = lane, d1 = lane + 32;
    float c0 = 0.f, c1 = 0.f;
#pragma unroll
    for (int h = 0; h < N_HEADS; h++) {
        float lsum = 0.f;
        float o0 = 0.f, o1 = 0.f;
#pragma unroll
        for (int s = 0; s < N_SPLIT; s++) {
            const size_t pbase = ((size_t)h * N_SPLIT + s) * N_TOK + row;
            lsum += g_l[pbase];
            const float* p = g_ho + pbase * D_H;
            o0 += p[d0];
            o1 += p[d1];
        }
        float w = aw[h] / lsum;
        c0 += w * o0;
        c1 += w * o1;
    }
    c0 *= ainv; c1 *= ainv;

    float s = c0 + c1;
#pragma unroll
    for (int w = 16; w; w >>= 1) s += __shfl_xor_sync(0xffffffffu, s, w);
    float mu = s * (1.f / 64.f);
    float v0 = c0 - mu, v1 = c1 - mu;
    float vv = v0 * v0 + v1 * v1;
#pragma unroll
    for (int w = 16; w; w >>= 1) vv += __shfl_xor_sync(0xffffffffu, vv, w);
    float inv = rsqrtf(vv * (1.f / 64.f) + LN_EPS);
    float n0 = v0 * inv * gamma[d0] + beta[d0];
    float n1 = v1 * inv * gamma[d1] + beta[d1];

    float o[N_CLS];
#pragma unroll
    for (int c = 0; c < N_CLS; c++)
        o[c] = n0 * fcw[d0 * N_CLS + c] + n1 * fcw[d1 * N_CLS + c];
#pragma unroll
    for (int c = 0; c < N_CLS; c++)
#pragma unroll
        for (int w = 16; w; w >>= 1) o[c] += __shfl_xor_sync(0xffffffffu, o[c], w);

    if (lane == 0) {
#pragma unroll
        for (int c = 0; c < N_CLS; c++)
            out[(size_t)row * N_CLS + c] = o[c] + fcb[c];
    }
}

// ---------------------------------------------------------------------------
extern "C" void kernel_launch(void* const* d_in, const int* in_sizes, int n_in,
                              void* d_out, int out_size)
{
    const float* x      = (const float*)d_in[0];
    const float* proj_w = (const float*)d_in[1];
    const float* proj_b = (const float*)d_in[2];
    const float* head_w = (const float*)d_in[3];
    const float* head_b = (const float*)d_in[4];
    const float* attn_w = (const float*)d_in[5];
    const float* gamma  = (const float*)d_in[6];
    const float* beta   = (const float*)d_in[7];
    const float* fc_w   = (const float*)d_in[8];
    const float* fc_b   = (const float*)d_in[9];
    float* out = (float*)d_out;

    static int smem_set = 0;
    if (!smem_set) {
        cudaFuncSetAttribute(k_attn, cudaFuncAttributeMaxDynamicSharedMemorySize, SM_TOTAL);
        smem_set = 1;
    }

    k_proj<<<N_TOK / 64, 256>>>(x, proj_w, proj_b, head_w, head_b);

    k_dummy<<<1, 32>>>();
    k_dummy<<<1, 32>>>();   // aligns ncu -s 5 onto k_attn

    dim3 g2(N_TOK / 128, N_HEADS, N_SPLIT);
    k_attn<<<g2, 544, SM_TOTAL>>>();

    k_final<<<N_TOK / 8, 256>>>(attn_w, gamma, beta, fc_w, fc_b, out);
}